// round 5
// baseline (speedup 1.0000x reference)
#include <cuda_runtime.h>
#include <cuda_bf16.h>
#include <cuda_fp16.h>
#include <cstdint>

#define N_NODES 50000
#define N_EDGES 800000
#define IN_F    512
#define OUT_F   96
#define ALPHA   0.1f
#define ITERS   10

// ---------------- device scratch ----------------
__device__ float  g_support[N_NODES * OUT_F];   // fp32 residual source
__device__ __half g_h0[N_NODES * OUT_F];        // fp16 ping
__device__ __half g_h1[N_NODES * OUT_F];        // fp16 pong
__device__ int    g_counts[N_NODES];
__device__ int    g_rowptr[N_NODES + 1];
__device__ int    g_offsets[N_NODES];
__device__ int    g_col[N_EDGES];
__device__ float  g_val[N_EDGES];
__device__ int    g_bsum[64];

__device__ __forceinline__ uint32_t smem_u32(const void* p) {
    uint32_t a;
    asm("{ .reg .u64 t; cvta.to.shared.u64 t, %1; cvt.u32.u64 %0, t; }" : "=r"(a) : "l"(p));
    return a;
}

// ---------------- CSR build ----------------
__global__ void zero_counts_kernel() {
    int i = blockIdx.x * blockDim.x + threadIdx.x;
    if (i < N_NODES) g_counts[i] = 0;
}
__global__ void hist_kernel(const int* __restrict__ dst) {
    int e = blockIdx.x * blockDim.x + threadIdx.x;
    if (e < N_EDGES) atomicAdd(&g_counts[dst[e]], 1);
}

#define SCAN_B 1024
#define N_SCAN_BLOCKS ((N_NODES + SCAN_B - 1) / SCAN_B)   // 49

__global__ void scan_block_kernel() {
    __shared__ int sh[SCAN_B];
    int tid = threadIdx.x;
    int i = blockIdx.x * SCAN_B + tid;
    int v = (i < N_NODES) ? g_counts[i] : 0;
    sh[tid] = v;
    __syncthreads();
    #pragma unroll
    for (int off = 1; off < SCAN_B; off <<= 1) {
        int t = (tid >= off) ? sh[tid - off] : 0;
        __syncthreads();
        sh[tid] += t;
        __syncthreads();
    }
    if (i < N_NODES) g_rowptr[i] = sh[tid] - v;     // block-local exclusive
    if (tid == SCAN_B - 1) g_bsum[blockIdx.x] = sh[tid];
}

// merged: block-offset scan (49 vals, serial per block) + add + rowptr tail
__global__ void scan_add_kernel() {
    __shared__ int pre[N_SCAN_BLOCKS + 1];
    int tid = threadIdx.x;
    if (tid == 0) {
        int acc = 0;
        #pragma unroll 1
        for (int b = 0; b < N_SCAN_BLOCKS; b++) { pre[b] = acc; acc += g_bsum[b]; }
        pre[N_SCAN_BLOCKS] = acc;
    }
    __syncthreads();
    int i = blockIdx.x * SCAN_B + tid;
    if (i < N_NODES) {
        int v = g_rowptr[i] + pre[blockIdx.x];
        g_rowptr[i] = v;
        g_offsets[i] = v;
    }
    if (blockIdx.x == 0 && tid == 0) g_rowptr[N_NODES] = pre[N_SCAN_BLOCKS];
}

__global__ void scatter_kernel(const int* __restrict__ src,
                               const int* __restrict__ dst,
                               const float* __restrict__ val) {
    int e = blockIdx.x * blockDim.x + threadIdx.x;
    if (e < N_EDGES) {
        int d = dst[e];
        int pos = atomicAdd(&g_offsets[d], 1);
        g_col[pos] = src[e];
        g_val[pos] = val[e] * (1.0f - ALPHA);
    }
}

// ---------------- HMMA GEMM: g_support = x @ W ----------------
// 3-term bf16 split: D = xh@Wh + xh@Wl + xl@Wh  (fp32 accumulate)
#define BM 128
#define BK 32
#define APAD 40

__device__ __forceinline__ void ldmat4(uint32_t* r, uint32_t addr) {
    asm volatile("ldmatrix.sync.aligned.m8n8.x4.shared.b16 {%0,%1,%2,%3}, [%4];"
                 : "=r"(r[0]), "=r"(r[1]), "=r"(r[2]), "=r"(r[3]) : "r"(addr));
}
__device__ __forceinline__ void mma16816(float* c, const uint32_t* a,
                                         uint32_t b0, uint32_t b1) {
    asm volatile("mma.sync.aligned.m16n8k16.row.col.f32.bf16.bf16.f32 "
                 "{%0,%1,%2,%3}, {%4,%5,%6,%7}, {%8,%9}, {%0,%1,%2,%3};"
                 : "+f"(c[0]), "+f"(c[1]), "+f"(c[2]), "+f"(c[3])
                 : "r"(a[0]), "r"(a[1]), "r"(a[2]), "r"(a[3]), "r"(b0), "r"(b1));
}

__global__ __launch_bounds__(256) void gemm_mma_kernel(const float* __restrict__ x,
                                                       const float* __restrict__ w) {
    __shared__ __nv_bfloat16 Ahi[BM * APAD];
    __shared__ __nv_bfloat16 Alo[BM * APAD];
    __shared__ __nv_bfloat16 Bhi[OUT_F * APAD];   // n-major: Bhi[n*APAD + k]
    __shared__ __nv_bfloat16 Blo[OUT_F * APAD];

    int tid = threadIdx.x;
    int wid = tid >> 5;
    int lane = tid & 31;
    int row0 = blockIdx.x * BM;

    float acc[12][4];
    #pragma unroll
    for (int j = 0; j < 12; j++)
        #pragma unroll
        for (int q = 0; q < 4; q++) acc[j][q] = 0.0f;

    uint32_t ahi_base = smem_u32(Ahi);
    uint32_t alo_base = smem_u32(Alo);

    int lm_row = wid * 16 + (lane & 7) + ((lane >> 3) & 1) * 8;
    int lm_k8  = (lane >> 4) * 8;
    int bn = lane >> 2;
    int bk = (lane & 3) * 2;

    for (int c = 0; c < IN_F / BK; c++) {
        int k0g = c * BK;

        {   // A tile: 128 rows x 32 k, split hi/lo
            int r = tid >> 1;
            int kh = (tid & 1) * 16;
            int gr = row0 + r;
            const float4* src = reinterpret_cast<const float4*>(
                &x[(long)gr * IN_F + k0g + kh]);
            #pragma unroll
            for (int q = 0; q < 4; q++) {
                float4 v = (gr < N_NODES) ? src[q]
                                          : make_float4(0.f, 0.f, 0.f, 0.f);
                float vv[4] = {v.x, v.y, v.z, v.w};
                __nv_bfloat162 th2[2], tl2[2];
                #pragma unroll
                for (int p = 0; p < 4; p++) {
                    __nv_bfloat16 h = __float2bfloat16(vv[p]);
                    __nv_bfloat16 l = __float2bfloat16(vv[p] - __bfloat162float(h));
                    if (p & 1) { th2[p >> 1].y = h; tl2[p >> 1].y = l; }
                    else       { th2[p >> 1].x = h; tl2[p >> 1].x = l; }
                }
                int o = r * APAD + kh + q * 4;
                *reinterpret_cast<__nv_bfloat162*>(&Ahi[o])     = th2[0];
                *reinterpret_cast<__nv_bfloat162*>(&Ahi[o + 2]) = th2[1];
                *reinterpret_cast<__nv_bfloat162*>(&Alo[o])     = tl2[0];
                *reinterpret_cast<__nv_bfloat162*>(&Alo[o + 2]) = tl2[1];
            }
        }

        #pragma unroll
        for (int j = 0; j < 12; j++) {   // W tile: 32 k x 96 n -> [n][k]
            int idx = j * 256 + tid;
            int k = idx / OUT_F;
            int n = idx - k * OUT_F;
            float v = w[(long)(k0g + k) * OUT_F + n];
            __nv_bfloat16 h = __float2bfloat16(v);
            __nv_bfloat16 l = __float2bfloat16(v - __bfloat162float(h));
            Bhi[n * APAD + k] = h;
            Blo[n * APAD + k] = l;
        }
        __syncthreads();

        #pragma unroll
        for (int ks = 0; ks < 2; ks++) {
            uint32_t a_off = (uint32_t)(lm_row * APAD + ks * 16 + lm_k8) * 2;
            uint32_t ah[4], al[4];
            ldmat4(ah, ahi_base + a_off);
            ldmat4(al, alo_base + a_off);
            int kk = ks * 16 + bk;
            #pragma unroll
            for (int j = 0; j < 12; j++) {
                int n = j * 8 + bn;
                uint32_t bh0 = *reinterpret_cast<const uint32_t*>(&Bhi[n * APAD + kk]);
                uint32_t bh1 = *reinterpret_cast<const uint32_t*>(&Bhi[n * APAD + kk + 8]);
                uint32_t bl0 = *reinterpret_cast<const uint32_t*>(&Blo[n * APAD + kk]);
                uint32_t bl1 = *reinterpret_cast<const uint32_t*>(&Blo[n * APAD + kk + 8]);
                mma16816(acc[j], ah, bh0, bh1);
                mma16816(acc[j], ah, bl0, bl1);
                mma16816(acc[j], al, bh0, bh1);
            }
        }
        __syncthreads();
    }

    int r0 = row0 + wid * 16 + (lane >> 2);
    int cb = (lane & 3) * 2;
    #pragma unroll
    for (int j = 0; j < 12; j++) {
        int cc = j * 8 + cb;
        if (r0 < N_NODES) {
            float2 t = make_float2(acc[j][0], acc[j][1]);
            *reinterpret_cast<float2*>(&g_support[(long)r0 * OUT_F + cc]) = t;
        }
        if (r0 + 8 < N_NODES) {
            float2 t = make_float2(acc[j][2], acc[j][3]);
            *reinterpret_cast<float2*>(&g_support[(long)(r0 + 8) * OUT_F + cc]) = t;
        }
    }
}

// ---------------- SPMM + residual + relu (fp16 intermediates) ----------------
// in_sel: 0 = g_support (fp32), 1 = g_h0, 2 = g_h1
// out_sel: 1 = g_h0, 2 = g_h1, 3 = d_out (fp32)
__global__ __launch_bounds__(256) void spmm_kernel(float* __restrict__ dout,
                                                   int in_sel, int out_sel) {
    int warp = (blockIdx.x * blockDim.x + threadIdx.x) >> 5;
    int lane = threadIdx.x & 31;
    if (warp >= N_NODES) return;

    int beg = g_rowptr[warp];
    int end = g_rowptr[warp + 1];

    float a0 = 0.0f, a1 = 0.0f, a2 = 0.0f;

    if (in_sel == 0) {
        const float* __restrict__ h = g_support;
        int e = beg;
        for (; e + 2 <= end; e += 2) {
            int s0 = __ldg(&g_col[e]);
            int s1 = __ldg(&g_col[e + 1]);
            float v0 = __ldg(&g_val[e]);
            float v1 = __ldg(&g_val[e + 1]);
            const float* p0 = h + (long)s0 * OUT_F;
            const float* p1 = h + (long)s1 * OUT_F;
            float x00 = p0[lane], x01 = p0[lane + 32], x02 = p0[lane + 64];
            float x10 = p1[lane], x11 = p1[lane + 32], x12 = p1[lane + 64];
            a0 = fmaf(v0, x00, a0); a1 = fmaf(v0, x01, a1); a2 = fmaf(v0, x02, a2);
            a0 = fmaf(v1, x10, a0); a1 = fmaf(v1, x11, a1); a2 = fmaf(v1, x12, a2);
        }
        if (e < end) {
            int s = __ldg(&g_col[e]);
            float v = __ldg(&g_val[e]);
            const float* p = h + (long)s * OUT_F;
            a0 = fmaf(v, p[lane], a0);
            a1 = fmaf(v, p[lane + 32], a1);
            a2 = fmaf(v, p[lane + 64], a2);
        }
    } else {
        const __half* __restrict__ h = (in_sel == 1) ? g_h0 : g_h1;
        int e = beg;
        for (; e + 2 <= end; e += 2) {
            int s0 = __ldg(&g_col[e]);
            int s1 = __ldg(&g_col[e + 1]);
            float v0 = __ldg(&g_val[e]);
            float v1 = __ldg(&g_val[e + 1]);
            const __half* p0 = h + (long)s0 * OUT_F;
            const __half* p1 = h + (long)s1 * OUT_F;
            float x00 = __half2float(p0[lane]);
            float x01 = __half2float(p0[lane + 32]);
            float x02 = __half2float(p0[lane + 64]);
            float x10 = __half2float(p1[lane]);
            float x11 = __half2float(p1[lane + 32]);
            float x12 = __half2float(p1[lane + 64]);
            a0 = fmaf(v0, x00, a0); a1 = fmaf(v0, x01, a1); a2 = fmaf(v0, x02, a2);
            a0 = fmaf(v1, x10, a0); a1 = fmaf(v1, x11, a1); a2 = fmaf(v1, x12, a2);
        }
        if (e < end) {
            int s = __ldg(&g_col[e]);
            float v = __ldg(&g_val[e]);
            const __half* p = h + (long)s * OUT_F;
            a0 = fmaf(v, __half2float(p[lane]), a0);
            a1 = fmaf(v, __half2float(p[lane + 32]), a1);
            a2 = fmaf(v, __half2float(p[lane + 64]), a2);
        }
    }

    long o = (long)warp * OUT_F + lane;
    float r0 = fmaxf(fmaf(ALPHA, g_support[o],      a0), 0.0f);
    float r1 = fmaxf(fmaf(ALPHA, g_support[o + 32], a1), 0.0f);
    float r2 = fmaxf(fmaf(ALPHA, g_support[o + 64], a2), 0.0f);

    if (out_sel == 3) {
        dout[o] = r0; dout[o + 32] = r1; dout[o + 64] = r2;
    } else {
        __half* out = (out_sel == 1) ? g_h0 : g_h1;
        out[o]      = __float2half_rn(r0);
        out[o + 32] = __float2half_rn(r1);
        out[o + 64] = __float2half_rn(r2);
    }
}

// ---------------- launch ----------------
extern "C" void kernel_launch(void* const* d_in, const int* in_sizes, int n_in,
                              void* d_out, int out_size) {
    const float* x  = (const float*)d_in[0];
    const float* w  = (const float*)d_in[1];
    const int* esrc = (const int*)d_in[2];
    const int* edst = (const int*)d_in[3];
    const float* ev = (const float*)d_in[4];
    float* dout = (float*)d_out;

    // CSR build
    zero_counts_kernel<<<(N_NODES + 255) / 256, 256>>>();
    hist_kernel<<<(N_EDGES + 255) / 256, 256>>>(edst);
    scan_block_kernel<<<N_SCAN_BLOCKS, SCAN_B>>>();
    scan_add_kernel<<<N_SCAN_BLOCKS, SCAN_B>>>();
    scatter_kernel<<<(N_EDGES + 255) / 256, 256>>>(esrc, edst, ev);

    // support = x @ W  (HMMA, 3-term bf16 split)
    gemm_mma_kernel<<<(N_NODES + BM - 1) / BM, 256>>>(x, w);

    // 10 propagation iterations:
    //   it1: support(fp32) -> h0(fp16)
    //   it k (2..9): h[k&1] -> h[(k+1)&1]
    //   it10: h0 -> d_out(fp32)
    int spmm_blocks = (N_NODES * 32 + 255) / 256;
    for (int it = 1; it <= ITERS; it++) {
        int in_sel  = (it == 1) ? 0 : ((it & 1) == 0 ? 1 : 2);
        int out_sel = (it == ITERS) ? 3 : (((it + 1) & 1) == 0 ? 2 : 1);
        spmm_kernel<<<spmm_blocks, 256>>>(dout, in_sel, out_sel);
    }
}

// round 6
// speedup vs baseline: 1.0202x; 1.0202x over previous
#include <cuda_runtime.h>
#include <cuda_bf16.h>
#include <cuda_fp16.h>
#include <cstdint>

#define N_NODES 50000
#define N_EDGES 800000
#define IN_F    512
#define OUT_F   96
#define ALPHA   0.1f
#define ITERS   10

// ---------------- device scratch ----------------
__device__ float  g_support[N_NODES * OUT_F];       // fp32 residual source
__device__ __half g_h0[N_NODES * OUT_F];            // fp16 ping
__device__ __half g_h1[N_NODES * OUT_F];            // fp16 pong
__device__ int    g_counts[N_NODES];
__device__ int    g_rowptr[N_NODES + 1];
__device__ int    g_offsets[N_NODES];
__device__ int2   g_edge[N_EDGES];                  // (col, val-bits) packed
__device__ int    g_bsum[64];

__device__ __forceinline__ uint32_t smem_u32(const void* p) {
    uint32_t a;
    asm("{ .reg .u64 t; cvta.to.shared.u64 t, %1; cvt.u32.u64 %0, t; }" : "=r"(a) : "l"(p));
    return a;
}

// ---------------- CSR build ----------------
__global__ void zero_counts_kernel() {
    int i = blockIdx.x * blockDim.x + threadIdx.x;
    if (i < N_NODES) g_counts[i] = 0;
}
__global__ void hist_kernel(const int* __restrict__ dst) {
    int e = blockIdx.x * blockDim.x + threadIdx.x;
    if (e < N_EDGES) atomicAdd(&g_counts[dst[e]], 1);
}

#define SCAN_B 1024
#define N_SCAN_BLOCKS ((N_NODES + SCAN_B - 1) / SCAN_B)   // 49

__global__ void scan_block_kernel() {
    __shared__ int sh[SCAN_B];
    int tid = threadIdx.x;
    int i = blockIdx.x * SCAN_B + tid;
    int v = (i < N_NODES) ? g_counts[i] : 0;
    sh[tid] = v;
    __syncthreads();
    #pragma unroll
    for (int off = 1; off < SCAN_B; off <<= 1) {
        int t = (tid >= off) ? sh[tid - off] : 0;
        __syncthreads();
        sh[tid] += t;
        __syncthreads();
    }
    if (i < N_NODES) g_rowptr[i] = sh[tid] - v;     // block-local exclusive
    if (tid == SCAN_B - 1) g_bsum[blockIdx.x] = sh[tid];
}

// merged: block-offset scan (49 vals, serial) + add + rowptr tail
__global__ void scan_add_kernel() {
    __shared__ int pre[N_SCAN_BLOCKS + 1];
    int tid = threadIdx.x;
    if (tid == 0) {
        int acc = 0;
        #pragma unroll 1
        for (int b = 0; b < N_SCAN_BLOCKS; b++) { pre[b] = acc; acc += g_bsum[b]; }
        pre[N_SCAN_BLOCKS] = acc;
    }
    __syncthreads();
    int i = blockIdx.x * SCAN_B + tid;
    if (i < N_NODES) {
        int v = g_rowptr[i] + pre[blockIdx.x];
        g_rowptr[i] = v;
        g_offsets[i] = v;
    }
    if (blockIdx.x == 0 && tid == 0) g_rowptr[N_NODES] = pre[N_SCAN_BLOCKS];
}

__global__ void scatter_kernel(const int* __restrict__ src,
                               const int* __restrict__ dst,
                               const float* __restrict__ val) {
    int e = blockIdx.x * blockDim.x + threadIdx.x;
    if (e < N_EDGES) {
        int d = dst[e];
        int pos = atomicAdd(&g_offsets[d], 1);
        g_edge[pos] = make_int2(src[e], __float_as_int(val[e] * (1.0f - ALPHA)));
    }
}

// ---------------- HMMA GEMM: g_support = x @ W ----------------
// 3-term bf16 split: D = xh@Wh + xh@Wl + xl@Wh  (fp32 accumulate)
#define BM 128
#define BK 32
#define APAD 40

__device__ __forceinline__ void ldmat4(uint32_t* r, uint32_t addr) {
    asm volatile("ldmatrix.sync.aligned.m8n8.x4.shared.b16 {%0,%1,%2,%3}, [%4];"
                 : "=r"(r[0]), "=r"(r[1]), "=r"(r[2]), "=r"(r[3]) : "r"(addr));
}
__device__ __forceinline__ void mma16816(float* c, const uint32_t* a,
                                         uint32_t b0, uint32_t b1) {
    asm volatile("mma.sync.aligned.m16n8k16.row.col.f32.bf16.bf16.f32 "
                 "{%0,%1,%2,%3}, {%4,%5,%6,%7}, {%8,%9}, {%0,%1,%2,%3};"
                 : "+f"(c[0]), "+f"(c[1]), "+f"(c[2]), "+f"(c[3])
                 : "r"(a[0]), "r"(a[1]), "r"(a[2]), "r"(a[3]), "r"(b0), "r"(b1));
}

__global__ __launch_bounds__(256) void gemm_mma_kernel(const float* __restrict__ x,
                                                       const float* __restrict__ w) {
    __shared__ __nv_bfloat16 Ahi[BM * APAD];
    __shared__ __nv_bfloat16 Alo[BM * APAD];
    __shared__ __nv_bfloat16 Bhi[OUT_F * APAD];   // n-major: Bhi[n*APAD + k]
    __shared__ __nv_bfloat16 Blo[OUT_F * APAD];

    int tid = threadIdx.x;
    int wid = tid >> 5;
    int lane = tid & 31;
    int row0 = blockIdx.x * BM;

    float acc[12][4];
    #pragma unroll
    for (int j = 0; j < 12; j++)
        #pragma unroll
        for (int q = 0; q < 4; q++) acc[j][q] = 0.0f;

    uint32_t ahi_base = smem_u32(Ahi);
    uint32_t alo_base = smem_u32(Alo);

    int lm_row = wid * 16 + (lane & 7) + ((lane >> 3) & 1) * 8;
    int lm_k8  = (lane >> 4) * 8;
    int bn = lane >> 2;
    int bk = (lane & 3) * 2;

    for (int c = 0; c < IN_F / BK; c++) {
        int k0g = c * BK;

        {   // A tile: 128 rows x 32 k, split hi/lo
            int r = tid >> 1;
            int kh = (tid & 1) * 16;
            int gr = row0 + r;
            const float4* src = reinterpret_cast<const float4*>(
                &x[(long)gr * IN_F + k0g + kh]);
            #pragma unroll
            for (int q = 0; q < 4; q++) {
                float4 v = (gr < N_NODES) ? src[q]
                                          : make_float4(0.f, 0.f, 0.f, 0.f);
                float vv[4] = {v.x, v.y, v.z, v.w};
                __nv_bfloat162 th2[2], tl2[2];
                #pragma unroll
                for (int p = 0; p < 4; p++) {
                    __nv_bfloat16 h = __float2bfloat16(vv[p]);
                    __nv_bfloat16 l = __float2bfloat16(vv[p] - __bfloat162float(h));
                    if (p & 1) { th2[p >> 1].y = h; tl2[p >> 1].y = l; }
                    else       { th2[p >> 1].x = h; tl2[p >> 1].x = l; }
                }
                int o = r * APAD + kh + q * 4;
                *reinterpret_cast<__nv_bfloat162*>(&Ahi[o])     = th2[0];
                *reinterpret_cast<__nv_bfloat162*>(&Ahi[o + 2]) = th2[1];
                *reinterpret_cast<__nv_bfloat162*>(&Alo[o])     = tl2[0];
                *reinterpret_cast<__nv_bfloat162*>(&Alo[o + 2]) = tl2[1];
            }
        }

        #pragma unroll
        for (int j = 0; j < 12; j++) {   // W tile: 32 k x 96 n -> [n][k]
            int idx = j * 256 + tid;
            int k = idx / OUT_F;
            int n = idx - k * OUT_F;
            float v = w[(long)(k0g + k) * OUT_F + n];
            __nv_bfloat16 h = __float2bfloat16(v);
            __nv_bfloat16 l = __float2bfloat16(v - __bfloat162float(h));
            Bhi[n * APAD + k] = h;
            Blo[n * APAD + k] = l;
        }
        __syncthreads();

        #pragma unroll
        for (int ks = 0; ks < 2; ks++) {
            uint32_t a_off = (uint32_t)(lm_row * APAD + ks * 16 + lm_k8) * 2;
            uint32_t ah[4], al[4];
            ldmat4(ah, ahi_base + a_off);
            ldmat4(al, alo_base + a_off);
            int kk = ks * 16 + bk;
            #pragma unroll
            for (int j = 0; j < 12; j++) {
                int n = j * 8 + bn;
                uint32_t bh0 = *reinterpret_cast<const uint32_t*>(&Bhi[n * APAD + kk]);
                uint32_t bh1 = *reinterpret_cast<const uint32_t*>(&Bhi[n * APAD + kk + 8]);
                uint32_t bl0 = *reinterpret_cast<const uint32_t*>(&Blo[n * APAD + kk]);
                uint32_t bl1 = *reinterpret_cast<const uint32_t*>(&Blo[n * APAD + kk + 8]);
                mma16816(acc[j], ah, bh0, bh1);
                mma16816(acc[j], ah, bl0, bl1);
                mma16816(acc[j], al, bh0, bh1);
            }
        }
        __syncthreads();
    }

    int r0 = row0 + wid * 16 + (lane >> 2);
    int cb = (lane & 3) * 2;
    #pragma unroll
    for (int j = 0; j < 12; j++) {
        int cc = j * 8 + cb;
        if (r0 < N_NODES) {
            float2 t = make_float2(acc[j][0], acc[j][1]);
            *reinterpret_cast<float2*>(&g_support[(long)r0 * OUT_F + cc]) = t;
        }
        if (r0 + 8 < N_NODES) {
            float2 t = make_float2(acc[j][2], acc[j][3]);
            *reinterpret_cast<float2*>(&g_support[(long)(r0 + 8) * OUT_F + cc]) = t;
        }
    }
}

// ---------------- SPMM + residual + relu (half2-packed intermediates) -------
// Lane owns feature pair {2*lane, 2*lane+1}; lanes 0-15 additionally own
// pair {64+2*lane, 64+2*lane+1}. Warp gather = one 128B load + one 64B load.
// in_sel: 0 = g_support (fp32), 1 = g_h0, 2 = g_h1
// out_sel: 1 = g_h0, 2 = g_h1, 3 = d_out (fp32)
__global__ __launch_bounds__(256) void spmm_kernel(float* __restrict__ dout,
                                                   int in_sel, int out_sel) {
    int row = (blockIdx.x * blockDim.x + threadIdx.x) >> 5;
    int lane = threadIdx.x & 31;
    if (row >= N_NODES) return;

    int beg = g_rowptr[row];
    int end = g_rowptr[row + 1];
    bool lo = lane < 16;

    float a00 = 0.f, a01 = 0.f, a10 = 0.f, a11 = 0.f;

    if (in_sel == 0) {
        const float2* __restrict__ h = reinterpret_cast<const float2*>(g_support);
        int e = beg;
        for (; e + 2 <= end; e += 2) {
            int2 e0 = __ldg(&g_edge[e]);
            int2 e1 = __ldg(&g_edge[e + 1]);
            float v0 = __int_as_float(e0.y);
            float v1 = __int_as_float(e1.y);
            const float2* p0 = h + (long)e0.x * 48;
            const float2* p1 = h + (long)e1.x * 48;
            float2 f00 = __ldg(p0 + lane);
            float2 f10 = __ldg(p1 + lane);
            float2 f01 = lo ? __ldg(p0 + 32 + lane) : make_float2(0.f, 0.f);
            float2 f11 = lo ? __ldg(p1 + 32 + lane) : make_float2(0.f, 0.f);
            a00 = fmaf(v0, f00.x, a00); a01 = fmaf(v0, f00.y, a01);
            a10 = fmaf(v0, f01.x, a10); a11 = fmaf(v0, f01.y, a11);
            a00 = fmaf(v1, f10.x, a00); a01 = fmaf(v1, f10.y, a01);
            a10 = fmaf(v1, f11.x, a10); a11 = fmaf(v1, f11.y, a11);
        }
        if (e < end) {
            int2 e0 = __ldg(&g_edge[e]);
            float v0 = __int_as_float(e0.y);
            const float2* p0 = h + (long)e0.x * 48;
            float2 f00 = __ldg(p0 + lane);
            float2 f01 = lo ? __ldg(p0 + 32 + lane) : make_float2(0.f, 0.f);
            a00 = fmaf(v0, f00.x, a00); a01 = fmaf(v0, f00.y, a01);
            a10 = fmaf(v0, f01.x, a10); a11 = fmaf(v0, f01.y, a11);
        }
    } else {
        const __half2* __restrict__ h = reinterpret_cast<const __half2*>(
            (in_sel == 1) ? g_h0 : g_h1);
        int e = beg;
        for (; e + 2 <= end; e += 2) {
            int2 e0 = __ldg(&g_edge[e]);
            int2 e1 = __ldg(&g_edge[e + 1]);
            float v0 = __int_as_float(e0.y);
            float v1 = __int_as_float(e1.y);
            const __half2* p0 = h + (long)e0.x * 48;
            const __half2* p1 = h + (long)e1.x * 48;
            __half2 u00 = __ldg(p0 + lane);
            __half2 u10 = __ldg(p1 + lane);
            __half2 u01 = lo ? __ldg(p0 + 32 + lane) : __half2();
            __half2 u11 = lo ? __ldg(p1 + 32 + lane) : __half2();
            float2 f00 = __half22float2(u00);
            float2 f01 = __half22float2(u01);
            float2 f10 = __half22float2(u10);
            float2 f11 = __half22float2(u11);
            a00 = fmaf(v0, f00.x, a00); a01 = fmaf(v0, f00.y, a01);
            a10 = fmaf(v0, f01.x, a10); a11 = fmaf(v0, f01.y, a11);
            a00 = fmaf(v1, f10.x, a00); a01 = fmaf(v1, f10.y, a01);
            a10 = fmaf(v1, f11.x, a10); a11 = fmaf(v1, f11.y, a11);
        }
        if (e < end) {
            int2 e0 = __ldg(&g_edge[e]);
            float v0 = __int_as_float(e0.y);
            const __half2* p0 = h + (long)e0.x * 48;
            __half2 u00 = __ldg(p0 + lane);
            __half2 u01 = lo ? __ldg(p0 + 32 + lane) : __half2();
            float2 f00 = __half22float2(u00);
            float2 f01 = __half22float2(u01);
            a00 = fmaf(v0, f00.x, a00); a01 = fmaf(v0, f00.y, a01);
            a10 = fmaf(v0, f01.x, a10); a11 = fmaf(v0, f01.y, a11);
        }
    }

    // residual + relu
    long ob = (long)row * OUT_F;
    float2 s0 = *reinterpret_cast<const float2*>(&g_support[ob + 2 * lane]);
    float r00 = fmaxf(fmaf(ALPHA, s0.x, a00), 0.0f);
    float r01 = fmaxf(fmaf(ALPHA, s0.y, a01), 0.0f);
    float r10 = 0.f, r11 = 0.f;
    if (lo) {
        float2 s1 = *reinterpret_cast<const float2*>(&g_support[ob + 64 + 2 * lane]);
        r10 = fmaxf(fmaf(ALPHA, s1.x, a10), 0.0f);
        r11 = fmaxf(fmaf(ALPHA, s1.y, a11), 0.0f);
    }

    if (out_sel == 3) {
        *reinterpret_cast<float2*>(&dout[ob + 2 * lane]) = make_float2(r00, r01);
        if (lo)
            *reinterpret_cast<float2*>(&dout[ob + 64 + 2 * lane]) = make_float2(r10, r11);
    } else {
        __half2* out = reinterpret_cast<__half2*>(((out_sel == 1) ? g_h0 : g_h1) + ob);
        out[lane] = __floats2half2_rn(r00, r01);
        if (lo) out[32 + lane] = __floats2half2_rn(r10, r11);
    }
}

// ---------------- launch ----------------
extern "C" void kernel_launch(void* const* d_in, const int* in_sizes, int n_in,
                              void* d_out, int out_size) {
    const float* x  = (const float*)d_in[0];
    const float* w  = (const float*)d_in[1];
    const int* esrc = (const int*)d_in[2];
    const int* edst = (const int*)d_in[3];
    const float* ev = (const float*)d_in[4];
    float* dout = (float*)d_out;

    // CSR build
    zero_counts_kernel<<<(N_NODES + 255) / 256, 256>>>();
    hist_kernel<<<(N_EDGES + 255) / 256, 256>>>(edst);
    scan_block_kernel<<<N_SCAN_BLOCKS, SCAN_B>>>();
    scan_add_kernel<<<N_SCAN_BLOCKS, SCAN_B>>>();
    scatter_kernel<<<(N_EDGES + 255) / 256, 256>>>(esrc, edst, ev);

    // support = x @ W  (HMMA, 3-term bf16 split)
    gemm_mma_kernel<<<(N_NODES + BM - 1) / BM, 256>>>(x, w);

    // 10 propagation iterations:
    //   it1: support(fp32) -> h0 ; it2..9 ping-pong ; it10: h0 -> d_out(fp32)
    int spmm_blocks = (N_NODES * 32 + 255) / 256;
    for (int it = 1; it <= ITERS; it++) {
        int in_sel  = (it == 1) ? 0 : ((it & 1) == 0 ? 1 : 2);
        int out_sel = (it == ITERS) ? 3 : (((it + 1) & 1) == 0 ? 2 : 1);
        spmm_kernel<<<spmm_blocks, 256>>>(dout, in_sel, out_sel);
    }
}